// round 17
// baseline (speedup 1.0000x reference)
#include <cuda_runtime.h>
#include <cstdint>

// Fused: conv3d(16->32, k3, pad1) + bias + maxpool(2x2x2) + logsumexp(ch) + relu
// x: (16,16,32,64,64) f32, w: (32,16,3,3,3) f32, bias: (32) f32
// out: (16,1,16,32,32) f32
//
// R16 (revert R15 phases; back to R14 structure, best=1157.6us):
//  f32x2 lanes now = two adjacent conv-w positions (cw,cw+1), NOT two channels.
//  -> x operand = naturally contiguous float2 (aligned LDS.64, zero pack MOVs for
//     kw=0,2; one mov.b64 for the kw=1 middle pair).
//  -> weights pre-DUPLICATED in the rearrange kernel: 32B per (ic,tap,g) =
//     {wg,wg, wg+8,wg+8, wg+16,wg+16, wg+24,wg+24}; two LDS.128 per tap.
//  Per thread: 4 channels x 2x2x2 pool window, 16 f32x2 accumulators.
//  x tile plain f32 (46KB, loaded once) + 2-stage cp.async weight ring (13.8KB)
//  = 59.9KB -> 3 blocks/SM.

#define TOH 4
#define TOW 8
#define SMEM_X_FLOATS (16 * 4 * 10 * 18)          // 11520 floats = 46080 B
#define W_STAGE_U2    432                         // 27 taps x 8 g x 32B = 6912 B
#define SMEM_BYTES    (SMEM_X_FLOATS * 4 + 2 * W_STAGE_U2 * 16)   // 59904 B

typedef unsigned long long ull;

__device__ __align__(16) float g_wre[27648];      // dup-rearranged weights (110.6 KB)

__device__ __forceinline__ ull pack_pair(float lo, float hi) {
    ull d;
    asm("mov.b64 %0, {%1, %2};" : "=l"(d) : "f"(lo), "f"(hi));
    return d;
}

__device__ __forceinline__ void fma2(ull& a, ull b, ull c) {
    // packed dual-fp32 FMA (Blackwell f32x2 pipe)
    asm("fma.rn.f32x2 %0, %1, %2, %3;" : "=l"(a) : "l"(b), "l"(c), "l"(a));
}

__device__ __forceinline__ uint32_t smem_u32(const void* p) {
    uint32_t a;
    asm("{ .reg .u64 t; cvta.to.shared.u64 t, %1; cvt.u32.u64 %0, t; }"
        : "=r"(a) : "l"(p));
    return a;
}

__device__ __forceinline__ void cp16(uint32_t dst, const void* src) {
    asm volatile("cp.async.cg.shared.global [%0], [%1], 16;\n"
                 :: "r"(dst), "l"(src));
}

__global__ void rearrange_w_kernel(const float* __restrict__ w) {
    int j = blockIdx.x * 256 + threadIdx.x;     // 27648 entries
    if (j < 27648) {
        int ic  = j / 1728;
        int r   = j - ic * 1728;
        int tap = r >> 6;                        // 0..26
        int q   = r & 63;
        int g   = q >> 3;                        // 0..7
        int s   = (q >> 1) & 3;                  // channel slot 0..3
        int oc  = g + s * 8;                     // g, g+8, g+16, g+24
        g_wre[j] = w[oc * 432 + ic * 27 + tap];  // each value written twice (q&1)
    }
}

struct Row { ull q[3]; };   // x pairs for kw=0,1,2: (x0,x1),(x1,x2),(x2,x3)

__global__ __launch_bounds__(256, 3)
void conv_pool_lse_kernel(const float* __restrict__ x,
                          const float* __restrict__ bias,
                          float* __restrict__ out) {
    extern __shared__ char smem[];
    float* xs = reinterpret_cast<float*>(smem);                          // [16][4][10][18]
    ulonglong2* wring =
        reinterpret_cast<ulonglong2*>(smem + SMEM_X_FLOATS * 4);         // [2][432]

    const int tid = threadIdx.x;
    const int bz = blockIdx.z;
    const int b  = bz >> 4;
    const int od = bz & 15;
    const int OH0 = blockIdx.y * TOH;
    const int OW0 = blockIdx.x * TOW;

    // ---- prefetch ic=0 weight slice into stage 0 (overlaps x-tile load) ----
    for (int i = tid; i < W_STAGE_U2; i += 256)
        cp16(smem_u32(wring + i), reinterpret_cast<const char*>(g_wre) + i * 16);
    asm volatile("cp.async.commit_group;\n");

    // ---- x tile (halo + zero pad): xs[ic][xd][xh][xw], 4x10x18 per ic ----
    {
        const int d0 = od * 2 - 1;
        const int h0 = OH0 * 2 - 1;
        const int w0 = OW0 * 2 - 1;
        const float* xb = x + (long)b * (16 * 32 * 64 * 64);
        for (int i = tid; i < SMEM_X_FLOATS; i += 256) {
            int ic = i / 720;
            int r  = i - ic * 720;
            int xd = r / 180; r -= xd * 180;
            int xh = r / 18;
            int xw = r - xh * 18;
            int gd = d0 + xd, gh = h0 + xh, gw = w0 + xw;
            float v = 0.0f;
            if ((unsigned)gd < 32u && (unsigned)gh < 64u && (unsigned)gw < 64u)
                v = xb[((ic * 32 + gd) * 64 + gh) * 64 + gw];
            xs[i] = v;
        }
    }

    // ---- main compute ----
    const int g   = tid & 7;           // oc group: channels g, g+8, g+16, g+24
    const int pos = tid >> 3;          // 0..31 pooled positions
    const int ph  = pos >> 3;          // 0..3
    const int pw  = pos & 7;           // 0..7
    const int ch  = ph * 2;            // conv-row base within tile (0..6)
    const int cw  = pw * 2;            // conv-col base; f32x2 lanes = (cw, cw+1)

    ull acc[4][2][2];                  // [channel][dd][hh], lanes = conv-w pair
#pragma unroll
    for (int c = 0; c < 4; ++c)
#pragma unroll
        for (int i = 0; i < 2; ++i)
#pragma unroll
            for (int j = 0; j < 2; ++j) acc[c][i][j] = 0ull;

#pragma unroll 1
    for (int ic = 0; ic < 16; ++ic) {
        // prefetch next ic weight slice, wait for current slice
        if (ic < 15) {
            for (int i = tid; i < W_STAGE_U2; i += 256)
                cp16(smem_u32(wring + ((ic + 1) & 1) * W_STAGE_U2 + i),
                     reinterpret_cast<const char*>(g_wre + (ic + 1) * 1728) + i * 16);
            asm volatile("cp.async.commit_group;\n");
            asm volatile("cp.async.wait_group 1;\n");
        } else {
            asm volatile("cp.async.wait_group 0;\n");
        }
        __syncthreads();   // weight stage + (first iter) x tile visible

        const float* xsl = xs + ic * 720;
        const ulonglong2* wbg = wring + (ic & 1) * W_STAGE_U2 + g * 2;

        auto loadrow = [&](Row& r, const float* p) {
            float2 a = *reinterpret_cast<const float2*>(p);      // (x0,x1) aligned
            float2 c = *reinterpret_cast<const float2*>(p + 2);  // (x2,x3) aligned
            r.q[0] = *reinterpret_cast<const ull*>(&a);
            r.q[2] = *reinterpret_cast<const ull*>(&c);
            r.q[1] = pack_pair(a.y, c.x);                        // (x1,x2)
        };
        auto taps = [&](int xd, int kh, const Row& A, const Row& B) {
#pragma unroll
            for (int dd = 0; dd < 2; ++dd) {
                const int kd = xd - dd;
                if (kd < 0 || kd > 2) continue;
#pragma unroll
                for (int kw = 0; kw < 3; ++kw) {
                    const int tap = kd * 9 + kh * 3 + kw;
                    ulonglong2 w0 = wbg[tap * 16 + 0];   // {dup(g), dup(g+8)}
                    ulonglong2 w1 = wbg[tap * 16 + 1];   // {dup(g+16), dup(g+24)}
                    fma2(acc[0][dd][0], w0.x, A.q[kw]);
                    fma2(acc[0][dd][1], w0.x, B.q[kw]);
                    fma2(acc[1][dd][0], w0.y, A.q[kw]);
                    fma2(acc[1][dd][1], w0.y, B.q[kw]);
                    fma2(acc[2][dd][0], w1.x, A.q[kw]);
                    fma2(acc[2][dd][1], w1.x, B.q[kw]);
                    fma2(acc[3][dd][0], w1.y, A.q[kw]);
                    fma2(acc[3][dd][1], w1.y, B.q[kw]);
                }
            }
        };

#pragma unroll
        for (int xd = 0; xd < 4; ++xd) {
            const float* rp = xsl + xd * 180 + ch * 18 + cw;
            // rolling 2-row window: rows ch..ch+3 feed kh = 0..2
            Row r0, r1, r2, r3;
            loadrow(r0, rp);
            loadrow(r1, rp + 18);
            taps(xd, 0, r0, r1);
            loadrow(r2, rp + 36);
            taps(xd, 1, r1, r2);
            loadrow(r3, rp + 54);
            taps(xd, 2, r2, r3);
        }
        __syncthreads();   // all warps done with this weight stage before overwrite
    }

    // ---- maxpool: over 2x2x2 accs AND the two f32x2 lanes; + bias ----
    float m[4];
#pragma unroll
    for (int c = 0; c < 4; ++c) {
        float mc = -3.0e38f;
#pragma unroll
        for (int i = 0; i < 2; ++i)
#pragma unroll
            for (int j = 0; j < 2; ++j) {
                ull a = acc[c][i][j];
                mc = fmaxf(mc, __uint_as_float((unsigned)a));
                mc = fmaxf(mc, __uint_as_float((unsigned)(a >> 32)));
            }
        m[c] = mc + bias[g + c * 8];
    }

    // ---- logsumexp over 32 channels (8 lanes x 4 channels each) + relu ----
    float mm = fmaxf(fmaxf(m[0], m[1]), fmaxf(m[2], m[3]));
#pragma unroll
    for (int msk = 4; msk; msk >>= 1)
        mm = fmaxf(mm, __shfl_xor_sync(0xffffffffu, mm, msk));
    float s = expf(m[0] - mm) + expf(m[1] - mm) + expf(m[2] - mm) + expf(m[3] - mm);
#pragma unroll
    for (int msk = 4; msk; msk >>= 1)
        s += __shfl_xor_sync(0xffffffffu, s, msk);

    if (g == 0) {
        float r = mm + logf(s);
        out[((b * 16 + od) * 32 + (OH0 + ph)) * 32 + (OW0 + pw)] = fmaxf(r, 0.0f);
    }
}

extern "C" void kernel_launch(void* const* d_in, const int* in_sizes, int n_in,
                              void* d_out, int out_size) {
    (void)in_sizes; (void)n_in; (void)out_size;
    const float* x    = (const float*)d_in[0];
    const float* w    = (const float*)d_in[1];
    const float* bias = (const float*)d_in[2];
    float* out        = (float*)d_out;

    // 1) rearrange + duplicate weights into the cp.async-friendly layout
    rearrange_w_kernel<<<108, 256>>>(w);

    // 2) fused kernel: x tile in smem, dup-weight slices via cp.async ring
    (void)cudaFuncSetAttribute(conv_pool_lse_kernel,
                               cudaFuncAttributeMaxDynamicSharedMemorySize, SMEM_BYTES);
    dim3 grid(32 / TOW, 32 / TOH, 16 * 16);   // (4 ow tiles, 8 oh tiles, b*od)
    conv_pool_lse_kernel<<<grid, 256, SMEM_BYTES>>>(x, bias, out);
}